// round 1
// baseline (speedup 1.0000x reference)
#include <cuda_runtime.h>
#include <cuda_bf16.h>
#include <math.h>

// Problem constants
#define D_MODEL 1024
#define N_HEADS 16
#define N_GROUPS 4
#define HEAD_DIM 64
#define KV_HEADS 4
#define D_KV 256
#define BATCH 2
#define SEQ 2048
#define BS (BATCH * SEQ)   // 4096

// Scratch buffers (device globals: no allocation allowed)
__device__ float g_Q[BS * D_MODEL];   // 16 MB
__device__ float g_K[BS * D_KV];      // 4 MB
__device__ float g_V[BS * D_KV];      // 4 MB
__device__ float g_O[BS * D_MODEL];   // 16 MB

// ---------------------------------------------------------------------------
// Tiled SGEMM: C[M,N] = A[M,K] @ B[K,N] + bias[N]
// BM=64, BN=64, BK=16, 256 threads, each computes 4x4.
// Assumes 64 | M, 64 | N, 16 | K.
// ---------------------------------------------------------------------------
__global__ __launch_bounds__(256) void sgemm_bias_kernel(
    const float* __restrict__ A, const float* __restrict__ B,
    const float* __restrict__ bias, float* __restrict__ C,
    int M, int N, int K)
{
    __shared__ float As[64][16];
    __shared__ float Bs[16][64];

    int tid = threadIdx.x;
    int ty = tid >> 4;      // 0..15
    int tx = tid & 15;      // 0..15
    int row0 = blockIdx.y * 64;
    int col0 = blockIdx.x * 64;

    // load indices
    int ar = tid >> 2;            // 0..63
    int ac = (tid & 3) * 4;       // 0,4,8,12
    int br = tid >> 4;            // 0..15
    int bc = (tid & 15) * 4;      // 0..60

    float acc[4][4];
    #pragma unroll
    for (int i = 0; i < 4; i++)
        #pragma unroll
        for (int j = 0; j < 4; j++) acc[i][j] = 0.f;

    for (int k0 = 0; k0 < K; k0 += 16) {
        float4 av = *(const float4*)(A + (size_t)(row0 + ar) * K + k0 + ac);
        float4 bv = *(const float4*)(B + (size_t)(k0 + br) * N + col0 + bc);
        *(float4*)(&As[ar][ac]) = av;
        *(float4*)(&Bs[br][bc]) = bv;
        __syncthreads();

        #pragma unroll
        for (int kk = 0; kk < 16; kk++) {
            float a[4], b[4];
            #pragma unroll
            for (int i = 0; i < 4; i++) a[i] = As[ty * 4 + i][kk];
            #pragma unroll
            for (int j = 0; j < 4; j++) b[j] = Bs[kk][tx * 4 + j];
            #pragma unroll
            for (int i = 0; i < 4; i++)
                #pragma unroll
                for (int j = 0; j < 4; j++)
                    acc[i][j] = fmaf(a[i], b[j], acc[i][j]);
        }
        __syncthreads();
    }

    #pragma unroll
    for (int i = 0; i < 4; i++) {
        int r = row0 + ty * 4 + i;
        #pragma unroll
        for (int j = 0; j < 4; j++) {
            int c = col0 + tx * 4 + j;
            C[(size_t)r * N + c] = acc[i][j] + bias[c];
        }
    }
}

// ---------------------------------------------------------------------------
// Flash attention (causal, GQA). One CTA = (b, h, 64-row q-tile).
// 128 threads. S=QK^T and O+=PV both use 4x8 register tiling (ty=tid/8,
// tx=tid%8). Softmax row-stats handled by thread pairs (tid/2 = row).
// ---------------------------------------------------------------------------
#define PAD 68   // row pitch (floats) for 64-wide smem tiles

__global__ __launch_bounds__(128) void fa_kernel(
    const float* __restrict__ Qb, const float* __restrict__ Kb,
    const float* __restrict__ Vb, float* __restrict__ Ob)
{
    extern __shared__ float sm[];
    float* Qs = sm;                    // 64*PAD
    float* Ks = sm + 64 * PAD;
    float* Vs = sm + 2 * 64 * PAD;
    float* Ss = sm + 3 * 64 * PAD;
    float* alpha_s = sm + 4 * 64 * PAD; // 64
    float* l_s = alpha_s + 64;          // 64

    int bh = blockIdx.x;               // 0..31
    int b = bh >> 4;
    int h = bh & 15;
    int kh = h >> 2;                   // kv head = h / N_GROUPS
    int qt = blockIdx.y;
    int q0 = qt * 64;
    int tid = threadIdx.x;

    // load Q tile [64 x 64]
    const float* Qg = Qb + ((size_t)(b * SEQ + q0)) * D_MODEL + h * HEAD_DIM;
    for (int idx = tid; idx < 64 * 64; idx += 128) {
        int r = idx >> 6, d = idx & 63;
        Qs[r * PAD + d] = Qg[(size_t)r * D_MODEL + d];
    }

    // softmax-owner mapping: 2 threads per row
    int srow = tid >> 1, shalf = tid & 1;
    float m_run = -INFINITY, l_run = 0.f;

    // gemm-tile mapping: 16x8 thread grid, each 4 rows x 8 cols
    int ty = tid >> 3, tx = tid & 7;
    int r0 = ty * 4, c0 = tx * 8;
    float acc[4][8];
    #pragma unroll
    for (int i = 0; i < 4; i++)
        #pragma unroll
        for (int j = 0; j < 8; j++) acc[i][j] = 0.f;

    const float scale = 0.125f;   // 1/sqrt(64)

    for (int kt = 0; kt <= qt; kt++) {
        int k0 = kt * 64;
        __syncthreads();   // protect K/V/Ss against previous iter readers

        const float* Kg = Kb + ((size_t)(b * SEQ + k0)) * D_KV + kh * HEAD_DIM;
        const float* Vg = Vb + ((size_t)(b * SEQ + k0)) * D_KV + kh * HEAD_DIM;
        for (int idx = tid; idx < 64 * 64; idx += 128) {
            int r = idx >> 6, d = idx & 63;
            Ks[r * PAD + d] = Kg[(size_t)r * D_KV + d];
            Vs[r * PAD + d] = Vg[(size_t)r * D_KV + d];
        }
        __syncthreads();

        // ---- S = Q K^T (register tiled) ----
        float s[4][8];
        #pragma unroll
        for (int i = 0; i < 4; i++)
            #pragma unroll
            for (int j = 0; j < 8; j++) s[i][j] = 0.f;

        #pragma unroll 8
        for (int d = 0; d < 64; d++) {
            float a[4], bb[8];
            #pragma unroll
            for (int i = 0; i < 4; i++) a[i] = Qs[(r0 + i) * PAD + d];
            #pragma unroll
            for (int j = 0; j < 8; j++) bb[j] = Ks[(c0 + j) * PAD + d];
            #pragma unroll
            for (int i = 0; i < 4; i++)
                #pragma unroll
                for (int j = 0; j < 8; j++)
                    s[i][j] = fmaf(a[i], bb[j], s[i][j]);
        }

        bool diag = (kt == qt);
        #pragma unroll
        for (int i = 0; i < 4; i++) {
            #pragma unroll
            for (int j = 0; j < 8; j++) {
                float v = s[i][j] * scale;
                if (diag && (c0 + j > r0 + i)) v = -INFINITY;  // k0==q0 on diag
                Ss[(r0 + i) * PAD + c0 + j] = v;
            }
        }
        __syncthreads();

        // ---- online softmax (2 threads per row) ----
        float pv[32];
        {
            const float* rowp = Ss + srow * PAD + shalf * 32;
            float tmax = -INFINITY;
            #pragma unroll
            for (int k = 0; k < 32; k++) {
                pv[k] = rowp[k];
                tmax = fmaxf(tmax, pv[k]);
            }
            tmax = fmaxf(tmax, __shfl_xor_sync(0xffffffffu, tmax, 1));
            float mnew = fmaxf(m_run, tmax);
            float tsum = 0.f;
            #pragma unroll
            for (int k = 0; k < 32; k++) {
                pv[k] = __expf(pv[k] - mnew);
                tsum += pv[k];
            }
            tsum += __shfl_xor_sync(0xffffffffu, tsum, 1);
            float alpha = __expf(m_run - mnew);
            l_run = l_run * alpha + tsum;
            m_run = mnew;
            float* roww = Ss + srow * PAD + shalf * 32;
            #pragma unroll
            for (int k = 0; k < 32; k++) roww[k] = pv[k];
            if (shalf == 0) alpha_s[srow] = alpha;
        }
        __syncthreads();

        // ---- O = alpha*O + P V (register tiled) ----
        float al[4];
        #pragma unroll
        for (int i = 0; i < 4; i++) al[i] = alpha_s[r0 + i];
        #pragma unroll
        for (int i = 0; i < 4; i++)
            #pragma unroll
            for (int j = 0; j < 8; j++) acc[i][j] *= al[i];

        #pragma unroll 8
        for (int j2 = 0; j2 < 64; j2++) {
            float p4[4], v8[8];
            #pragma unroll
            for (int i = 0; i < 4; i++) p4[i] = Ss[(r0 + i) * PAD + j2];
            #pragma unroll
            for (int j = 0; j < 8; j++) v8[j] = Vs[j2 * PAD + c0 + j];
            #pragma unroll
            for (int i = 0; i < 4; i++)
                #pragma unroll
                for (int j = 0; j < 8; j++)
                    acc[i][j] = fmaf(p4[i], v8[j], acc[i][j]);
        }
    }

    // publish row sums, normalize, write out
    if (shalf == 0) l_s[srow] = l_run;
    __syncthreads();

    float linv[4];
    #pragma unroll
    for (int i = 0; i < 4; i++) linv[i] = 1.0f / l_s[r0 + i];

    float* Og = Ob + ((size_t)(b * SEQ + q0)) * D_MODEL + h * HEAD_DIM;
    #pragma unroll
    for (int i = 0; i < 4; i++)
        #pragma unroll
        for (int j = 0; j < 8; j++)
            Og[(size_t)(r0 + i) * D_MODEL + c0 + j] = acc[i][j] * linv[i];
}

// ---------------------------------------------------------------------------
// Launch
// ---------------------------------------------------------------------------
extern "C" void kernel_launch(void* const* d_in, const int* in_sizes, int n_in,
                              void* d_out, int out_size)
{
    const float* x  = (const float*)d_in[0];
    const float* Wq = (const float*)d_in[1];
    const float* bq = (const float*)d_in[2];
    const float* Wk = (const float*)d_in[3];
    const float* bk = (const float*)d_in[4];
    const float* Wv = (const float*)d_in[5];
    const float* bv = (const float*)d_in[6];
    const float* Wo = (const float*)d_in[7];
    const float* bo = (const float*)d_in[8];
    // d_in[9] = mask (causal; computed implicitly)
    float* out = (float*)d_out;

    float *Qp, *Kp, *Vp, *Op;
    cudaGetSymbolAddress((void**)&Qp, g_Q);
    cudaGetSymbolAddress((void**)&Kp, g_K);
    cudaGetSymbolAddress((void**)&Vp, g_V);
    cudaGetSymbolAddress((void**)&Op, g_O);

    // projections
    {
        dim3 gq(D_MODEL / 64, BS / 64);
        sgemm_bias_kernel<<<gq, 256>>>(x, Wq, bq, Qp, BS, D_MODEL, D_MODEL);
        dim3 gkv(D_KV / 64, BS / 64);
        sgemm_bias_kernel<<<gkv, 256>>>(x, Wk, bk, Kp, BS, D_KV, D_MODEL);
        sgemm_bias_kernel<<<gkv, 256>>>(x, Wv, bv, Vp, BS, D_KV, D_MODEL);
    }

    // flash attention
    {
        size_t smem = (4 * 64 * PAD + 128) * sizeof(float);
        static bool attr_set = false;
        // setting an attribute is idempotent & deterministic; cheap to repeat
        cudaFuncSetAttribute(fa_kernel, cudaFuncAttributeMaxDynamicSharedMemorySize,
                             (int)smem);
        (void)attr_set;
        dim3 g(BATCH * N_HEADS, SEQ / 64);
        fa_kernel<<<g, 128, smem>>>(Qp, Kp, Vp, Op);
    }

    // output projection
    {
        dim3 go(D_MODEL / 64, BS / 64);
        sgemm_bias_kernel<<<go, 256>>>(Op, Wo, bo, out, BS, D_MODEL, D_MODEL);
    }
}